// round 5
// baseline (speedup 1.0000x reference)
#include <cuda_runtime.h>
#include <math_constants.h>

#define PI_F 3.14159265358979323846f

// Per-box intermediate results (N <= 8192 guard; actual N = 1024)
__device__ float        g_box_mean[8192];
__device__ int          g_box_valid[8192];
__device__ unsigned int g_done = 0;   // last-block ticket; reset by last block each call

__device__ __forceinline__ float frcp_approx(float x) {
    float r;
    asm("rcp.approx.f32 %0, %1;" : "=f"(r) : "f"(x));
    return r;
}

struct BoxConst {
    float k1, k2;
    float bs[4];
    float midx[4], halfx[4], midy[4], halfy[4];
};

// Process 4 points (q0,q1 hold xy pairs, d4 their densities) against the box.
__device__ __forceinline__ void process4(const BoxConst& C,
                                         float4 q0, float4 q1, float4 d4,
                                         float& lsum, int& lcnt) {
    const float PX[4] = {q0.x, q0.z, q1.x, q1.z};
    const float PY[4] = {q0.y, q0.w, q1.y, q1.w};
    const float DN[4] = {d4.x, d4.y, d4.z, d4.w};

#pragma unroll
    for (int h = 0; h < 4; h++) {
        const float px = (PX[h] == 0.0f) ? 0.0001f : PX[h];
        const float py = PY[h];
        const float slope = py * frcp_approx(px);

        const float rA = frcp_approx(slope - C.k1);   // edges 0, 2
        const float rB = frcp_approx(slope - C.k2);   // edges 1, 3

        float best_aix = CUDART_INF_F;   // argmin key: |ix| (monotone with cen)
        float best_dis = 0.0f;
        int   m = 0;

#pragma unroll
        for (int j = 0; j < 4; j++) {
            const float r  = (j & 1) ? rB : rA;
            const float ix = C.bs[j] * r;
            const float iy = ix * slope;
            const float dis = fabsf(ix - px) + fabsf(iy - py);
            const float irx = rintf(ix * 10000.0f);
            const float iry = rintf(iy * 10000.0f);
            const bool mask = (fabsf(irx - C.midx[j]) < C.halfx[j]) |
                              (fabsf(iry - C.midy[j]) < C.halfy[j]);
            m += mask ? 1 : 0;
            const bool better = mask & (fabsf(ix) < best_aix);
            best_aix = better ? fabsf(ix) : best_aix;
            best_dis = better ? dis : best_dis;
        }

        if (m == 2) {
            lsum += best_dis * frcp_approx(DN[h]);
            lcnt += 1;
        }
    }
}

__global__ void __launch_bounds__(128, 7)
box_kernel(const float* __restrict__ wl,
           const float* __restrict__ Ry,
           const float4* __restrict__ points4,   // 2 points per float4
           const float4* __restrict__ density4,  // 4 densities per float4
           const float* __restrict__ center,
           float* __restrict__ out,
           int P) {
    const int n = blockIdx.x;
    const int t = threadIdx.x;

    // setup: [0]=k1 [1]=k2 [2..5]=bs [6..9]=midx [10..13]=halfx [14..17]=midy [18..21]=halfy
    __shared__ float s_set[22];
    __shared__ int   s_last;

    if (t == 0) {
        const float w  = wl[2 * n];
        const float l  = wl[2 * n + 1];
        const float ry = Ry[n];
        const float c0 = center[2 * n];
        const float c1 = center[2 * n + 1];

        const float init_theta = atanf(w / l);
        const float length     = sqrtf(w * w + l * l) * 0.5f;

        float angs[4];
        angs[0] = init_theta + ry;
        angs[1] = PI_F - init_theta + ry;
        angs[2] = PI_F + init_theta + ry;
        angs[3] = -init_theta + ry;

        float cx[4], cy[4];
#pragma unroll
        for (int j = 0; j < 4; j++) {
            cx[j] = length * cosf(angs[j]) + c0;
            cy[j] = length * sinf(angs[j]) + c1;
        }

        float ry2 = ry;
        if (ry2 == PI_F * 0.5f) ry2 -= 0.0001f;
        if (ry2 == 0.0f)        ry2 += 0.0001f;
        const float k1 = tanf(ry2);
        const float k2 = tanf(ry2 + PI_F * 0.5f);

        s_set[0] = k1;
        s_set[1] = k2;
        // bs order = {b11, b22, b12, b21}
        s_set[2] = cy[0] - k1 * cx[0];   // b11
        s_set[3] = cy[2] - k2 * cx[2];   // b22
        s_set[4] = cy[2] - k1 * cx[2];   // b12
        s_set[5] = cy[0] - k2 * cx[0];   // b21

        float cxr[4], cyr[4];
#pragma unroll
        for (int j = 0; j < 4; j++) {
            cxr[j] = rintf(cx[j] * 10000.0f);
            cyr[j] = rintf(cy[j] * 10000.0f);
        }
        const int nxt[4] = {1, 2, 3, 0};
#pragma unroll
        for (int j = 0; j < 4; j++) {
            const int jn = nxt[j];
            const float lox = fminf(cxr[j], cxr[jn]);
            const float hix = fmaxf(cxr[j], cxr[jn]);
            const float loy = fminf(cyr[j], cyr[jn]);
            const float hiy = fmaxf(cyr[j], cyr[jn]);
            s_set[6  + j] = (lox + hix) * 0.5f;   // midx (exact: integer-valued bounds)
            s_set[10 + j] = (hix - lox) * 0.5f;   // halfx
            s_set[14 + j] = (loy + hiy) * 0.5f;   // midy
            s_set[18 + j] = (hiy - loy) * 0.5f;   // halfy
        }
    }
    __syncthreads();

    BoxConst C;
    C.k1 = s_set[0];
    C.k2 = s_set[1];
#pragma unroll
    for (int j = 0; j < 4; j++) {
        C.bs[j]    = s_set[2 + j];
        C.midx[j]  = s_set[6 + j];
        C.halfx[j] = s_set[10 + j];
        C.midy[j]  = s_set[14 + j];
        C.halfy[j] = s_set[18 + j];
    }

    const float4* pts4 = points4  + (size_t)n * (P / 2);
    const float4* dns4 = density4 + (size_t)n * (P / 4);

    float lsum = 0.0f;
    int   lcnt = 0;

    // 8 points per iteration: two 4-point units (i and i + P/8), loads front-batched.
    const int eighth = P / 8;
    for (int i = t; i < eighth; i += 128) {
        const int i2 = i + eighth;
        const float4 a0 = pts4[2 * i];
        const float4 a1 = pts4[2 * i + 1];
        const float4 b0 = pts4[2 * i2];
        const float4 b1 = pts4[2 * i2 + 1];
        const float4 da = dns4[i];
        const float4 db = dns4[i2];

        process4(C, a0, a1, da, lsum, lcnt);
        process4(C, b0, b1, db, lsum, lcnt);
    }

    // ---- block reduction (128 threads) ----
    __shared__ float ssum[128];
    __shared__ int   scnt[128];
    ssum[t] = lsum;
    scnt[t] = lcnt;
    __syncthreads();
#pragma unroll
    for (int off = 64; off > 0; off >>= 1) {
        if (t < off) {
            ssum[t] += ssum[t + off];
            scnt[t] += scnt[t + off];
        }
        __syncthreads();
    }

    if (t == 0) {
        const int cnt = scnt[0];
        g_box_valid[n] = (cnt >= 3) ? 1 : 0;
        g_box_mean[n]  = ssum[0] / (float)max(cnt, 1);
        __threadfence();
        const unsigned int ticket = atomicAdd(&g_done, 1u);
        s_last = (ticket == gridDim.x - 1) ? 1 : 0;
    }
    __syncthreads();

    // ---- fused finalize: only the last block to finish runs this ----
    if (s_last) {
        const int N = gridDim.x;
        float s = 0.0f;
        int   c = 0;
        for (int i = t; i < N; i += 128) {
            if (g_box_valid[i]) {
                s += g_box_mean[i];
                c += 1;
            }
        }
        ssum[t] = s;
        scnt[t] = c;
        __syncthreads();
#pragma unroll
        for (int off = 64; off > 0; off >>= 1) {
            if (t < off) {
                ssum[t] += ssum[t + off];
                scnt[t] += scnt[t + off];
            }
            __syncthreads();
        }
        if (t == 0) {
            out[0] = ssum[0] / (float)max(scnt[0], 1);
            g_done = 0;   // reset for next graph replay
        }
    }
}

extern "C" void kernel_launch(void* const* d_in, const int* in_sizes, int n_in,
                              void* d_out, int out_size) {
    const float*  wl      = (const float*)d_in[0];
    const float*  Ry      = (const float*)d_in[1];
    const float4* points4 = (const float4*)d_in[2];
    const float4* dens4   = (const float4*)d_in[3];
    const float*  center  = (const float*)d_in[4];
    float* out = (float*)d_out;

    const int N = in_sizes[1];        // Ry has N elements
    const int P = in_sizes[3] / N;    // density has N*P elements

    box_kernel<<<N, 128>>>(wl, Ry, points4, dens4, center, out, P);
}

// round 6
// speedup vs baseline: 1.1969x; 1.1969x over previous
#include <cuda_runtime.h>
#include <math_constants.h>

#define PI_F 3.14159265358979323846f

// Per-box intermediate results (N <= 8192 guard; actual N = 1024)
__device__ float        g_box_mean[8192];
__device__ int          g_box_valid[8192];
__device__ unsigned int g_done = 0;   // last-block ticket; reset by last block each call

__device__ __forceinline__ float frcp_approx(float x) {
    float r;
    asm("rcp.approx.f32 %0, %1;" : "=f"(r) : "f"(x));
    return r;
}

struct BoxConst {
    float k1, k2;
    float bs[4];
    float midx[4], halfx[4], midy[4], halfy[4];   // float-space bounds (pre-shrunk by 0.5 ulp of grid)
};

// Process 4 points (q0,q1 hold xy pairs, d4 their densities) against the box.
__device__ __forceinline__ void process4(const BoxConst& C,
                                         float4 q0, float4 q1, float4 d4,
                                         float& lsum, int& lcnt) {
    const float PX[4] = {q0.x, q0.z, q1.x, q1.z};
    const float PY[4] = {q0.y, q0.w, q1.y, q1.w};
    const float DN[4] = {d4.x, d4.y, d4.z, d4.w};

#pragma unroll
    for (int h = 0; h < 4; h++) {
        const float px = (PX[h] == 0.0f) ? 0.0001f : PX[h];
        const float py = PY[h];
        const float slope = py * frcp_approx(px);
        const float s1 = 1.0f + fabsf(slope);     // dis = |ix-px| * s1

        const float rA = frcp_approx(slope - C.k1);   // edges 0, 2
        const float rB = frcp_approx(slope - C.k2);   // edges 1, 3

        float best_aix = CUDART_INF_F;   // argmin key: |ix| (monotone with cen)
        float best_ix  = 0.0f;
        int   m = 0;

#pragma unroll
        for (int j = 0; j < 4; j++) {
            const float r  = (j & 1) ? rB : rA;
            const float ix = C.bs[j] * r;
            const float iy = ix * slope;
            // float-space mask: equivalent to the rint(1e4*...) integer test
            // except on measure-zero half-integer ties
            const bool mask = (fabsf(ix - C.midx[j]) < C.halfx[j]) |
                              (fabsf(iy - C.midy[j]) < C.halfy[j]);
            m += mask ? 1 : 0;
            const bool better = mask & (fabsf(ix) < best_aix);
            best_aix = better ? fabsf(ix) : best_aix;
            best_ix  = better ? ix : best_ix;
        }

        if (m == 2) {
            const float dis = fabsf(best_ix - px) * s1;
            lsum = fmaf(dis, frcp_approx(DN[h]), lsum);
            lcnt += 1;
        }
    }
}

__global__ void __launch_bounds__(128, 7)
box_kernel(const float* __restrict__ wl,
           const float* __restrict__ Ry,
           const float4* __restrict__ points4,   // 2 points per float4
           const float4* __restrict__ density4,  // 4 densities per float4
           const float* __restrict__ center,
           float* __restrict__ out,
           int P) {
    const int n = blockIdx.x;
    const int t = threadIdx.x;

    // setup: [0]=k1 [1]=k2 [2..5]=bs [6..9]=midx [10..13]=halfx [14..17]=midy [18..21]=halfy
    __shared__ float s_set[22];
    __shared__ int   s_last;

    if (t == 0) {
        const float w  = wl[2 * n];
        const float l  = wl[2 * n + 1];
        const float ry = Ry[n];
        const float c0 = center[2 * n];
        const float c1 = center[2 * n + 1];

        const float init_theta = atanf(w / l);
        const float length     = sqrtf(w * w + l * l) * 0.5f;

        float angs[4];
        angs[0] = init_theta + ry;
        angs[1] = PI_F - init_theta + ry;
        angs[2] = PI_F + init_theta + ry;
        angs[3] = -init_theta + ry;

        float cx[4], cy[4];
#pragma unroll
        for (int j = 0; j < 4; j++) {
            cx[j] = length * cosf(angs[j]) + c0;
            cy[j] = length * sinf(angs[j]) + c1;
        }

        float ry2 = ry;
        if (ry2 == PI_F * 0.5f) ry2 -= 0.0001f;
        if (ry2 == 0.0f)        ry2 += 0.0001f;
        const float k1 = tanf(ry2);
        const float k2 = tanf(ry2 + PI_F * 0.5f);

        s_set[0] = k1;
        s_set[1] = k2;
        // bs order = {b11, b22, b12, b21}
        s_set[2] = cy[0] - k1 * cx[0];   // b11
        s_set[3] = cy[2] - k2 * cx[2];   // b22
        s_set[4] = cy[2] - k1 * cx[2];   // b12
        s_set[5] = cy[0] - k2 * cx[0];   // b21

        float cxr[4], cyr[4];
#pragma unroll
        for (int j = 0; j < 4; j++) {
            cxr[j] = rintf(cx[j] * 10000.0f);
            cyr[j] = rintf(cy[j] * 10000.0f);
        }
        const int nxt[4] = {1, 2, 3, 0};
#pragma unroll
        for (int j = 0; j < 4; j++) {
            const int jn = nxt[j];
            const float lox = fminf(cxr[j], cxr[jn]);
            const float hix = fmaxf(cxr[j], cxr[jn]);
            const float loy = fminf(cyr[j], cyr[jn]);
            const float hiy = fmaxf(cyr[j], cyr[jn]);
            // shrink by 0.5 (rint threshold), rescale to float space
            const float loxp = (lox + 0.5f) * 1e-4f;
            const float hixp = (hix - 0.5f) * 1e-4f;
            const float loyp = (loy + 0.5f) * 1e-4f;
            const float hiyp = (hiy - 0.5f) * 1e-4f;
            s_set[6  + j] = 0.5f * (loxp + hixp);   // midx
            s_set[10 + j] = 0.5f * (hixp - loxp);   // halfx (<=0 => always-false, matches ref)
            s_set[14 + j] = 0.5f * (loyp + hiyp);   // midy
            s_set[18 + j] = 0.5f * (hiyp - loyp);   // halfy
        }
    }
    __syncthreads();

    BoxConst C;
    C.k1 = s_set[0];
    C.k2 = s_set[1];
#pragma unroll
    for (int j = 0; j < 4; j++) {
        C.bs[j]    = s_set[2 + j];
        C.midx[j]  = s_set[6 + j];
        C.halfx[j] = s_set[10 + j];
        C.midy[j]  = s_set[14 + j];
        C.halfy[j] = s_set[18 + j];
    }

    const float4* pts4 = points4  + (size_t)n * (P / 2);
    const float4* dns4 = density4 + (size_t)n * (P / 4);

    float lsum = 0.0f;
    int   lcnt = 0;

    // 8 points per iteration: two 4-point units (i and i + P/8), loads front-batched.
    const int eighth = P / 8;
    for (int i = t; i < eighth; i += 128) {
        const int i2 = i + eighth;
        const float4 a0 = pts4[2 * i];
        const float4 a1 = pts4[2 * i + 1];
        const float4 b0 = pts4[2 * i2];
        const float4 b1 = pts4[2 * i2 + 1];
        const float4 da = dns4[i];
        const float4 db = dns4[i2];

        process4(C, a0, a1, da, lsum, lcnt);
        process4(C, b0, b1, db, lsum, lcnt);
    }

    // ---- block reduction (128 threads) ----
    __shared__ float ssum[128];
    __shared__ int   scnt[128];
    ssum[t] = lsum;
    scnt[t] = lcnt;
    __syncthreads();
#pragma unroll
    for (int off = 64; off > 0; off >>= 1) {
        if (t < off) {
            ssum[t] += ssum[t + off];
            scnt[t] += scnt[t + off];
        }
        __syncthreads();
    }

    if (t == 0) {
        const int cnt = scnt[0];
        g_box_valid[n] = (cnt >= 3) ? 1 : 0;
        g_box_mean[n]  = ssum[0] / (float)max(cnt, 1);
        __threadfence();
        const unsigned int ticket = atomicAdd(&g_done, 1u);
        s_last = (ticket == gridDim.x - 1) ? 1 : 0;
    }
    __syncthreads();

    // ---- fused finalize: only the last block to finish runs this ----
    if (s_last) {
        const int N = gridDim.x;
        float s = 0.0f;
        int   c = 0;
        for (int i = t; i < N; i += 128) {
            if (g_box_valid[i]) {
                s += g_box_mean[i];
                c += 1;
            }
        }
        ssum[t] = s;
        scnt[t] = c;
        __syncthreads();
#pragma unroll
        for (int off = 64; off > 0; off >>= 1) {
            if (t < off) {
                ssum[t] += ssum[t + off];
                scnt[t] += scnt[t + off];
            }
            __syncthreads();
        }
        if (t == 0) {
            out[0] = ssum[0] / (float)max(scnt[0], 1);
            g_done = 0;   // reset for next graph replay
        }
    }
}

extern "C" void kernel_launch(void* const* d_in, const int* in_sizes, int n_in,
                              void* d_out, int out_size) {
    const float*  wl      = (const float*)d_in[0];
    const float*  Ry      = (const float*)d_in[1];
    const float4* points4 = (const float4*)d_in[2];
    const float4* dens4   = (const float4*)d_in[3];
    const float*  center  = (const float*)d_in[4];
    float* out = (float*)d_out;

    const int N = in_sizes[1];        // Ry has N elements
    const int P = in_sizes[3] / N;    // density has N*P elements

    box_kernel<<<N, 128>>>(wl, Ry, points4, dens4, center, out, P);
}